// round 2
// baseline (speedup 1.0000x reference)
#include <cuda_runtime.h>
#include <cuda_bf16.h>

#define NMAX 512
#define DDIM 128
#define TA 4
#define MARGIN_F 0.1f

// Scratch (no allocations allowed in kernel_launch)
__device__ float g_enorm[NMAX * DDIM];
__device__ float g_sum;
__device__ float g_cnt;

// ---------------------------------------------------------------------------
// Kernel 1: row-normalize embeddings; block = one row (128 threads).
// Also zeroes the global accumulators (block 0) — stream-ordered before k2.
// ---------------------------------------------------------------------------
__global__ void normalize_kernel(const float* __restrict__ emb, int n) {
    int r = blockIdx.x;
    int t = threadIdx.x;  // 0..127
    float v = emb[r * DDIM + t];
    float ss = v * v;
    #pragma unroll
    for (int o = 16; o > 0; o >>= 1)
        ss += __shfl_xor_sync(0xffffffffu, ss, o);
    __shared__ float wss[4];
    if ((t & 31) == 0) wss[t >> 5] = ss;
    __syncthreads();
    float tot = wss[0] + wss[1] + wss[2] + wss[3];
    float inv = 1.0f / sqrtf(tot);
    g_enorm[r * DDIM + t] = v * inv;
    if (r == 0 && t == 0) { g_sum = 0.0f; g_cnt = 0.0f; }
}

// ---------------------------------------------------------------------------
// Kernel 2: per block handle TA anchors. Compute TA sim rows (dot products vs
// all n normalized rows), then accumulate triplet loss.
// Labels buffer dtype is detected at runtime (int32 vs int64): JAX with x64
// disabled canonicalizes jnp.int64 -> int32.
// ---------------------------------------------------------------------------
__global__ __launch_bounds__(256) void triplet_kernel(
    const int* __restrict__ labels_raw, int n) {
    __shared__ float s_anchor[TA][DDIM];
    __shared__ float s_sim[TA][NMAX];
    __shared__ int   s_lab[NMAX];
    __shared__ int   s_pos[NMAX];
    __shared__ int   s_npos;
    __shared__ int   s_oddor;
    __shared__ float s_red[256];

    const int t  = threadIdx.x;       // 256 threads
    const int a0 = blockIdx.x * TA;

    // --- dtype detection: OR of odd int32 words over the first n words ---
    if (t == 0) s_oddor = 0;
    __syncthreads();
    int oddacc = 0;
    for (int j = t; j < n; j += 256)
        if (j & 1) oddacc |= labels_raw[j];
    #pragma unroll
    for (int o = 16; o > 0; o >>= 1)
        oddacc |= __shfl_xor_sync(0xffffffffu, oddacc, o);
    if ((t & 31) == 0 && oddacc) atomicOr(&s_oddor, oddacc);
    __syncthreads();
    bool is_i32 = (s_oddor != 0);

    // labels -> smem
    for (int j = t; j < n; j += 256)
        s_lab[j] = is_i32 ? labels_raw[j] : labels_raw[2 * j];

    // anchor rows -> smem
    for (int i = t; i < TA * DDIM; i += 256) {
        int ar = i / DDIM, c = i % DDIM;
        int a = a0 + ar;
        s_anchor[ar][c] = (a < n) ? g_enorm[a * DDIM + c] : 0.0f;
    }
    __syncthreads();

    // sim rows: each thread owns columns t, t+256, ...
    for (int j = t; j < n; j += 256) {
        const float4* row = (const float4*)(g_enorm + (size_t)j * DDIM);
        float acc[TA];
        #pragma unroll
        for (int ar = 0; ar < TA; ar++) acc[ar] = 0.0f;
        #pragma unroll 4
        for (int c4 = 0; c4 < DDIM / 4; c4++) {
            float4 e = row[c4];
            #pragma unroll
            for (int ar = 0; ar < TA; ar++) {
                float4 av = ((const float4*)s_anchor[ar])[c4];
                acc[ar] += e.x * av.x + e.y * av.y + e.z * av.z + e.w * av.w;
            }
        }
        #pragma unroll
        for (int ar = 0; ar < TA; ar++) s_sim[ar][j] = acc[ar];
    }
    __syncthreads();

    float sum = 0.0f;
    float cnt = 0.0f;

    for (int ar = 0; ar < TA; ar++) {
        int a = a0 + ar;
        bool valid_a = (a < n);
        int la = valid_a ? s_lab[a] : -1;

        if (t == 0) s_npos = 0;
        __syncthreads();

        // positive list (order irrelevant)
        if (valid_a) {
            for (int j = t; j < n; j += 256) {
                if (j != a && s_lab[j] == la) {
                    int idx = atomicAdd(&s_npos, 1);
                    s_pos[idx] = j;
                }
            }
        }
        __syncthreads();
        int npos = s_npos;

        if (valid_a && npos > 0) {
            for (int nj = t; nj < n; nj += 256) {
                if (s_lab[nj] != la) {
                    float sn = s_sim[ar][nj] + MARGIN_F;
                    for (int pi = 0; pi < npos; pi++) {
                        float v = sn - s_sim[ar][s_pos[pi]];
                        float r = fmaxf(v, 0.0f);
                        sum += r;
                        cnt += (r > 1e-16f) ? 1.0f : 0.0f;
                    }
                }
            }
        }
        __syncthreads();  // protect s_pos/s_npos reuse
    }

    // block reduce sum
    s_red[t] = sum;
    __syncthreads();
    #pragma unroll
    for (int o = 128; o > 0; o >>= 1) {
        if (t < o) s_red[t] += s_red[t + o];
        __syncthreads();
    }
    if (t == 0) atomicAdd(&g_sum, s_red[0]);
    __syncthreads();

    // block reduce count
    s_red[t] = cnt;
    __syncthreads();
    #pragma unroll
    for (int o = 128; o > 0; o >>= 1) {
        if (t < o) s_red[t] += s_red[t + o];
        __syncthreads();
    }
    if (t == 0) atomicAdd(&g_cnt, s_red[0]);
}

// ---------------------------------------------------------------------------
// Kernel 3: finalize scalar
// ---------------------------------------------------------------------------
__global__ void finalize_kernel(float* __restrict__ out) {
    out[0] = g_sum / (g_cnt + 1e-16f);
}

extern "C" void kernel_launch(void* const* d_in, const int* in_sizes, int n_in,
                              void* d_out, int out_size) {
    const float* emb    = (const float*)d_in[0];
    const int*   labels = (const int*)d_in[1];
    float*       out    = (float*)d_out;

    int n = in_sizes[1];            // number of rows (labels count)
    if (n > NMAX) n = NMAX;         // scratch capacity guard

    normalize_kernel<<<n, DDIM>>>(emb, n);
    triplet_kernel<<<(n + TA - 1) / TA, 256>>>(labels, n);
    finalize_kernel<<<1, 1>>>(out);
}